// round 7
// baseline (speedup 1.0000x reference)
#include <cuda_runtime.h>
#include <cuda_fp16.h>
#include <math.h>
#include <stdint.h>

#define N_NODES   51200
#define NUM_AUD   64
#define NODES_PER 800
#define E_EDGES   409600
#define NEG       0.2f

// ---------------- scratch ----------------------------------------------------
__device__ __half g_h16[(size_t)N_NODES * 512];
__device__ __half g_mh[(size_t)N_NODES * 256];
__device__ __half g_x16[(size_t)N_NODES * 512];
__device__ __half g_w1t[512 * 512];
__device__ __half g_w2t[512 * 256];
__device__ float  g_alsp[(size_t)N_NODES * 4];   // 2 parts x [N,2]
__device__ float  g_aldp[(size_t)N_NODES * 4];
__device__ int    g_deg[N_NODES];
__device__ int    g_rowptr[N_NODES + 1];
__device__ int    g_cursor[N_NODES];
__device__ int    g_bucket[E_EDGES];
__device__ int    g_partial[128];

// ---------------- PTX helpers --------------------------------------------------
__device__ __forceinline__ uint32_t smem_u32(const void* p) {
    uint32_t a;
    asm("{ .reg .u64 t; cvta.to.shared.u64 t, %1; cvt.u32.u64 %0, t; }" : "=r"(a) : "l"(p));
    return a;
}
#define CP_ASYNC16(sa, ga) asm volatile("cp.async.cg.shared.global [%0], [%1], 16;" :: "r"(sa), "l"(ga))
#define CP_COMMIT()        asm volatile("cp.async.commit_group;" ::: "memory")
#define CP_WAIT(n)         asm volatile("cp.async.wait_group %0;" :: "n"(n) : "memory")

#define LDMATRIX_X4(r0, r1, r2, r3, ad) \
    asm volatile("ldmatrix.sync.aligned.m8n8.x4.shared.b16 {%0,%1,%2,%3}, [%4];" \
        : "=r"(r0), "=r"(r1), "=r"(r2), "=r"(r3) : "r"(ad))

#define MMA_FP16(c, a0, a1, a2, a3, b0, b1) \
    asm volatile("mma.sync.aligned.m16n8k16.row.col.f32.f16.f16.f32 " \
        "{%0,%1,%2,%3}, {%4,%5,%6,%7}, {%8,%9}, {%0,%1,%2,%3};" \
        : "+f"((c)[0]), "+f"((c)[1]), "+f"((c)[2]), "+f"((c)[3]) \
        : "r"(a0), "r"(a1), "r"(a2), "r"(a3), "r"(b0), "r"(b1))

// ---------------- fp16 GEMM (R5 config: 3-stage, 1 CTA/SM) ---------------------
#define ROWB   80
#define A_TILE (128 * ROWB)
#define B_TILE (128 * ROWB)
#define STAGE  (A_TILE + B_TILE)
#define NSTAGE 3
#define GEMM_SMEM (NSTAGE * STAGE + 1024)

__global__ void __launch_bounds__(256)
gemm_fp16_kernel(const __half* __restrict__ A, const __half* __restrict__ Bt,
                 __half* __restrict__ C,
                 const float* __restrict__ a_s, const float* __restrict__ a_d,
                 float* __restrict__ alsp, float* __restrict__ aldp, int K) {
    extern __shared__ char smem[];
    const uint32_t sb = smem_u32(smem);
    float* s_as = (float*)(smem + NSTAGE * STAGE);
    float* s_ad = s_as + 128;

    const int tid = threadIdx.x;
    const int lane = tid & 31;
    const int wid = tid >> 5;
    const int warp_m = wid >> 1;
    const int warp_n = wid & 1;
    const int n0 = blockIdx.x * 128;
    const int m0 = blockIdx.y * 128;
    const int head = n0 >> 8;
    const int nin = n0 & 255;
    const int part = (n0 >> 7) & 1;
    float* alsP = alsp + (size_t)part * N_NODES * 2;
    float* aldP = aldp + (size_t)part * N_NODES * 2;

    if (tid < 128) s_as[tid] = a_s[head * 256 + nin + tid];
    else           s_ad[tid - 128] = a_d[head * 256 + nin + tid - 128];

    const int ld_r = tid >> 2;
    const int ld_c = (tid & 3) << 4;

    const int a_row_l = warp_m * 32 + (lane & 15);
    const int a_colb  = (lane >> 4) << 4;
    const int bg = lane >> 3;
    const int b_row_base = warp_n * 64 + ((bg >> 1) << 3) + (lane & 7);
    const int b_colb  = (bg & 1) << 4;

    float acc[2][8][4];
#pragma unroll
    for (int i = 0; i < 2; ++i)
#pragma unroll
        for (int j = 0; j < 8; ++j)
#pragma unroll
            for (int k = 0; k < 4; ++k) acc[i][j][k] = 0.f;

    const int nch = K >> 5;

#define PREFETCH(CH) do { \
    const int k0 = (CH) << 5; \
    const uint32_t st = sb + ((CH) % NSTAGE) * STAGE; \
    _Pragma("unroll") \
    for (int hh = 0; hh < 2; ++hh) { \
        int r = ld_r + hh * 64; \
        CP_ASYNC16(st + r * ROWB + ld_c, A + (size_t)(m0 + r) * K + k0 + (ld_c >> 1)); \
    } \
    _Pragma("unroll") \
    for (int hh = 0; hh < 2; ++hh) { \
        int r = ld_r + hh * 64; \
        CP_ASYNC16(st + A_TILE + r * ROWB + ld_c, Bt + (size_t)(n0 + r) * K + k0 + (ld_c >> 1)); \
    } \
} while (0)

    PREFETCH(0); CP_COMMIT();
    PREFETCH(1); CP_COMMIT();

    for (int ch = 0; ch < nch; ++ch) {
        if (ch + 2 < nch) { PREFETCH(ch + 2); CP_COMMIT(); CP_WAIT(2); }
        else if (ch + 1 < nch) { CP_WAIT(1); }
        else { CP_WAIT(0); }
        __syncthreads();

        const uint32_t st = sb + (ch % NSTAGE) * STAGE;
#pragma unroll
        for (int ks = 0; ks < 2; ++ks) {
            const int kb = ks * 32;
            uint32_t a[2][4], b[4][4];
#pragma unroll
            for (int mt = 0; mt < 2; ++mt) {
                uint32_t ad = st + (a_row_l + mt * 16) * ROWB + kb + a_colb;
                LDMATRIX_X4(a[mt][0], a[mt][1], a[mt][2], a[mt][3], ad);
            }
#pragma unroll
            for (int np = 0; np < 4; ++np) {
                uint32_t ad = st + A_TILE + (b_row_base + np * 16) * ROWB + kb + b_colb;
                LDMATRIX_X4(b[np][0], b[np][1], b[np][2], b[np][3], ad);
            }
#pragma unroll
            for (int mt = 0; mt < 2; ++mt)
#pragma unroll
                for (int np = 0; np < 4; ++np)
#pragma unroll
                    for (int half = 0; half < 2; ++half)
                        MMA_FP16(acc[mt][np * 2 + half],
                                 a[mt][0], a[mt][1], a[mt][2], a[mt][3],
                                 b[np][half * 2], b[np][half * 2 + 1]);
        }
        __syncthreads();
    }

    // epilogue: fp16 store + attention-logit partials (plain stores, disjoint slices)
    const int g = lane >> 2;
    const int cpair = (lane & 3) << 1;
#pragma unroll
    for (int mt = 0; mt < 2; ++mt) {
        const int r0g = m0 + warp_m * 32 + mt * 16 + g;
        float ps0 = 0.f, pd0 = 0.f, ps1 = 0.f, pd1 = 0.f;
#pragma unroll
        for (int nt = 0; nt < 8; ++nt) {
            const int colL = warp_n * 64 + nt * 8 + cpair;
            float* c = acc[mt][nt];
            *(__half2*)(C + (size_t)r0g * 512 + n0 + colL) = __floats2half2_rn(c[0], c[1]);
            *(__half2*)(C + (size_t)(r0g + 8) * 512 + n0 + colL) = __floats2half2_rn(c[2], c[3]);
            ps0 += c[0] * s_as[colL] + c[1] * s_as[colL + 1];
            pd0 += c[0] * s_ad[colL] + c[1] * s_ad[colL + 1];
            ps1 += c[2] * s_as[colL] + c[3] * s_as[colL + 1];
            pd1 += c[2] * s_ad[colL] + c[3] * s_ad[colL + 1];
        }
#pragma unroll
        for (int o = 1; o <= 2; o <<= 1) {
            ps0 += __shfl_xor_sync(0xffffffffu, ps0, o);
            pd0 += __shfl_xor_sync(0xffffffffu, pd0, o);
            ps1 += __shfl_xor_sync(0xffffffffu, ps1, o);
            pd1 += __shfl_xor_sync(0xffffffffu, pd1, o);
        }
        // warp_n 0 and 1 cover disjoint column halves of the same (head,part)?
        // No: both warp_n halves are within the same 128-col block -> same part.
        // Reduce across the two warp_n warps via smem is avoided: instead each
        // warp_n handles 64 of the 128 cols, so combine with one extra shuffle:
        // lanes with lane&3==0 in warp_n=0/1 hold partial sums; sum via global
        // add would race. Use per-warp_n staging in smem:
        __shared__ float red[2][2][2][8][2];  // [warp_n][mt][pair(r0g/r0g+8)][warp_m*? ]
        // simpler: stage by (warp_m, warp_n, mt): 4*2*2 rows, each 8 lanes (g pairs)
        if ((lane & 3) == 0) {
            red[warp_n][mt][0][warp_m * 2 + (g >> 2)][0] = 0.f; // placeholder (unused)
        }
        // Fallback: atomic-free via two-step is complex; use atomicAdd only across
        // the 2 warp_n warps (2 atomics per row instead of global contention):
        if ((lane & 3) == 0) {
            atomicAdd(alsP + r0g * 2 + head, ps0);
            atomicAdd(aldP + r0g * 2 + head, pd0);
            atomicAdd(alsP + (r0g + 8) * 2 + head, ps1);
            atomicAdd(aldP + (r0g + 8) * 2 + head, pd1);
        }
    }
}

// ---------------- conversions ----------------------------------------------------
__global__ void conv_f2h_kernel(const float* __restrict__ in, __half* __restrict__ out, int n4) {
    int i = blockIdx.x * blockDim.x + threadIdx.x;
    if (i >= n4) return;
    float4 v = ((const float4*)in)[i];
    ((__half2*)out)[2 * i + 0] = __floats2half2_rn(v.x, v.y);
    ((__half2*)out)[2 * i + 1] = __floats2half2_rn(v.z, v.w);
}
__global__ void convT_f2h_kernel(const float* __restrict__ W, __half* __restrict__ Wt, int K, int Nn) {
    int o = blockIdx.x * blockDim.x + threadIdx.x;
    if (o >= K * Nn) return;
    int n = o / K, k = o - n * K;
    Wt[o] = __float2half(W[(size_t)k * Nn + n]);
}
__global__ void zero_parts_kernel(float* a, float* b, int n) {
    int i = blockIdx.x * blockDim.x + threadIdx.x;
    if (i < n) { a[i] = 0.f; b[i] = 0.f; }
}

// ---------------- CSR build --------------------------------------------------
__global__ void count_kernel(const int* __restrict__ dst) {
    int e = blockIdx.x * blockDim.x + threadIdx.x;
    if (e < E_EDGES) atomicAdd(&g_deg[dst[e]], 1);
}
__global__ void scan_local_kernel() {
    __shared__ int sh[512];
    int g = blockIdx.x * 512 + threadIdx.x;
    int v = g_deg[g];
    sh[threadIdx.x] = v;
    __syncthreads();
    for (int off = 1; off < 512; off <<= 1) {
        int t = (threadIdx.x >= off) ? sh[threadIdx.x - off] : 0;
        __syncthreads();
        sh[threadIdx.x] += t;
        __syncthreads();
    }
    g_rowptr[g] = sh[threadIdx.x] - v;
    if (threadIdx.x == 511) g_partial[blockIdx.x] = sh[511];
}
__global__ void scan_partial_kernel(int nb) {
    if (threadIdx.x == 0 && blockIdx.x == 0) {
        int acc = 0;
        for (int i = 0; i < nb; ++i) { int t = g_partial[i]; g_partial[i] = acc; acc += t; }
    }
}
__global__ void scan_add_kernel() {
    int g = blockIdx.x * 512 + threadIdx.x;
    int v = g_rowptr[g] + g_partial[blockIdx.x];
    g_rowptr[g] = v;
    g_cursor[g] = v;
    if (g == 0) g_rowptr[N_NODES] = E_EDGES;
}
__global__ void fill_kernel(const int* __restrict__ src, const int* __restrict__ dst) {
    int e = blockIdx.x * blockDim.x + threadIdx.x;
    if (e < E_EDGES) {
        int pos = atomicAdd(&g_cursor[dst[e]], 1);
        g_bucket[pos] = src[e];
    }
}

// ---------------- GAT aggregation ------------------------------------------------
__global__ void __launch_bounds__(256)
gat_aggregate_warp(const __half* __restrict__ h,
                   const float* __restrict__ alsp, const float* __restrict__ aldp,
                   const float* __restrict__ bias,
                   float* __restrict__ out32, __half* __restrict__ out16,
                   int do_relu) {
    __shared__ int   s_src[8][64];
    __shared__ float s_a0[8][64], s_a1[8][64];
    const int w = threadIdx.x >> 5, lane = threadIdx.x & 31;
    const int d = blockIdx.x * 8 + w;
    const int beg = g_rowptr[d];
    const int deg = g_rowptr[d + 1] - beg;
    const int tot = min(deg + 1, 64);
    const float* alsQ = alsp + (size_t)N_NODES * 2;
    const float* aldQ = aldp + (size_t)N_NODES * 2;
    const float ad0 = aldp[2 * d] + aldQ[2 * d];
    const float ad1 = aldp[2 * d + 1] + aldQ[2 * d + 1];

    float m0 = -INFINITY, m1 = -INFINITY;
    for (int k = lane; k < tot; k += 32) {
        int s = (k < deg) ? g_bucket[beg + k] : d;
        float e0 = alsp[2 * s] + alsQ[2 * s] + ad0;         e0 = e0 > 0.f ? e0 : NEG * e0;
        float e1 = alsp[2 * s + 1] + alsQ[2 * s + 1] + ad1; e1 = e1 > 0.f ? e1 : NEG * e1;
        s_src[w][k] = s;
        s_a0[w][k] = e0;
        s_a1[w][k] = e1;
        m0 = fmaxf(m0, e0);
        m1 = fmaxf(m1, e1);
    }
#pragma unroll
    for (int o = 16; o; o >>= 1) {
        m0 = fmaxf(m0, __shfl_xor_sync(0xffffffffu, m0, o));
        m1 = fmaxf(m1, __shfl_xor_sync(0xffffffffu, m1, o));
    }
    __syncwarp();
    float q0 = 0.f, q1 = 0.f;
    for (int k = lane; k < tot; k += 32) {
        float w0 = __expf(s_a0[w][k] - m0);
        float w1 = __expf(s_a1[w][k] - m1);
        s_a0[w][k] = w0;
        s_a1[w][k] = w1;
        q0 += w0;
        q1 += w1;
    }
#pragma unroll
    for (int o = 16; o; o >>= 1) {
        q0 += __shfl_xor_sync(0xffffffffu, q0, o);
        q1 += __shfl_xor_sync(0xffffffffu, q1, o);
    }
    const float inv0 = 1.f / q0, inv1 = 1.f / q1;
    __syncwarp();

    float2 acc0[4] = {}, acc1[4] = {};
    int   s_next = s_src[w][0];
    float a0_next = s_a0[w][0], a1_next = s_a1[w][0];
    for (int k = 0; k < tot; ++k) {
        const int s = s_next;
        const float al0 = a0_next * inv0;
        const float al1 = a1_next * inv1;
        if (k + 1 < tot) {
            s_next = s_src[w][k + 1];
            a0_next = s_a0[w][k + 1];
            a1_next = s_a1[w][k + 1];
        }
        const __half2* row = (const __half2*)(h + (size_t)s * 512) + lane;
#pragma unroll
        for (int j = 0; j < 4; ++j) {
            float2 v0 = __half22float2(row[32 * j]);
            float2 v1 = __half22float2(row[128 + 32 * j]);
            acc0[j].x += al0 * v0.x; acc0[j].y += al0 * v0.y;
            acc1[j].x += al1 * v1.x; acc1[j].y += al1 * v1.y;
        }
    }
#pragma unroll
    for (int j = 0; j < 4; ++j) {
        const int c = 2 * lane + 64 * j;
        float vx = 0.5f * (acc0[j].x + acc1[j].x) + bias[c];
        float vy = 0.5f * (acc0[j].y + acc1[j].y) + bias[c + 1];
        if (do_relu) { vx = fmaxf(vx, 0.f); vy = fmaxf(vy, 0.f); }
        if (out32) *(float2*)(out32 + (size_t)d * 256 + c) = make_float2(vx, vy);
        if (out16) *(__half2*)(out16 + (size_t)d * 256 + c) = __floats2half2_rn(vx, vy);
    }
}

// ---------------- temporal attention ------------------------------------------
__global__ void temporal_attn_kernel(const float* __restrict__ emb,
                                     const float* __restrict__ w_att,
                                     const float* __restrict__ b_att,
                                     const float* __restrict__ w_cls,
                                     const float* __restrict__ b_cls,
                                     float* __restrict__ out_audio) {
    const int a = blockIdx.x;
    const int tid = threadIdx.x;
    __shared__ float swa[256];
    __shared__ float slog[NODES_PER];
    __shared__ float sred[256];
    swa[tid] = w_att[tid];
    __syncthreads();
    const int base = a * NODES_PER;
    const int warp = tid >> 5, lane = tid & 31;
    for (int i = warp; i < NODES_PER; i += 8) {
        const float* row = emb + (size_t)(base + i) * 256;
        float p = 0.f;
#pragma unroll
        for (int c = lane; c < 256; c += 32) p += row[c] * swa[c];
#pragma unroll
        for (int o = 16; o; o >>= 1) p += __shfl_xor_sync(0xffffffffu, p, o);
        if (lane == 0) slog[i] = p + b_att[0];
    }
    __syncthreads();
    float m = -INFINITY;
    for (int i = tid; i < NODES_PER; i += 256) m = fmaxf(m, slog[i]);
    sred[tid] = m; __syncthreads();
    for (int o = 128; o; o >>= 1) { if (tid < o) sred[tid] = fmaxf(sred[tid], sred[tid + o]); __syncthreads(); }
    m = sred[0]; __syncthreads();
    float q = 0.f;
    for (int i = tid; i < NODES_PER; i += 256) { float w = expf(slog[i] - m); slog[i] = w; q += w; }
    sred[tid] = q; __syncthreads();
    for (int o = 128; o; o >>= 1) { if (tid < o) sred[tid] += sred[tid + o]; __syncthreads(); }
    float inv = 1.f / sred[0];
    __syncthreads();

    float ac0 = 0.f, ac1 = 0.f, ac2 = 0.f, ac3 = 0.f;
    for (int i = 0; i + 4 <= NODES_PER; i += 4) {
        ac0 += slog[i + 0] * emb[(size_t)(base + i + 0) * 256 + tid];
        ac1 += slog[i + 1] * emb[(size_t)(base + i + 1) * 256 + tid];
        ac2 += slog[i + 2] * emb[(size_t)(base + i + 2) * 256 + tid];
        ac3 += slog[i + 3] * emb[(size_t)(base + i + 3) * 256 + tid];
    }
    float acc = ((ac0 + ac1) + (ac2 + ac3)) * inv;

    float r0 = acc * w_cls[tid * 2 + 0];
    float r1 = acc * w_cls[tid * 2 + 1];
    sred[tid] = r0; __syncthreads();
    for (int o = 128; o; o >>= 1) { if (tid < o) sred[tid] += sred[tid + o]; __syncthreads(); }
    r0 = sred[0]; __syncthreads();
    sred[tid] = r1; __syncthreads();
    for (int o = 128; o; o >>= 1) { if (tid < o) sred[tid] += sred[tid + o]; __syncthreads(); }
    r1 = sred[0];
    if (tid == 0) {
        out_audio[a * 2 + 0] = r0 + b_cls[0];
        out_audio[a * 2 + 1] = r1 + b_cls[1];
    }
}

// ---------------- launch -------------------------------------------------------
extern "C" void kernel_launch(void* const* d_in, const int* in_sizes, int n_in,
                              void* d_out, int out_size) {
    const float* x     = (const float*)d_in[0];
    const int*   eidx  = (const int*)d_in[1];
    const float* W1    = (const float*)d_in[3];
    const float* a_s1  = (const float*)d_in[4];
    const float* a_d1  = (const float*)d_in[5];
    const float* b1    = (const float*)d_in[6];
    const float* W2    = (const float*)d_in[7];
    const float* a_s2  = (const float*)d_in[8];
    const float* a_d2  = (const float*)d_in[9];
    const float* b2    = (const float*)d_in[10];
    const float* w_att = (const float*)d_in[11];
    const float* b_att = (const float*)d_in[12];
    const float* w_cls = (const float*)d_in[13];
    const float* b_cls = (const float*)d_in[14];

    const int* src = eidx;
    const int* dst = eidx + E_EDGES;

    float* node_emb  = (float*)d_out;
    float* out_audio = (float*)d_out + (size_t)N_NODES * 256;

    void* p;
    cudaGetSymbolAddress(&p, g_h16);  __half* h16  = (__half*)p;
    cudaGetSymbolAddress(&p, g_mh);   __half* mh   = (__half*)p;
    cudaGetSymbolAddress(&p, g_x16);  __half* x16  = (__half*)p;
    cudaGetSymbolAddress(&p, g_w1t);  __half* w1t  = (__half*)p;
    cudaGetSymbolAddress(&p, g_w2t);  __half* w2t  = (__half*)p;
    cudaGetSymbolAddress(&p, g_alsp); float*  alsp = (float*)p;
    cudaGetSymbolAddress(&p, g_aldp); float*  aldp = (float*)p;
    cudaGetSymbolAddress(&p, g_deg);  int*    degp = (int*)p;

    cudaFuncSetAttribute(gemm_fp16_kernel, cudaFuncAttributeMaxDynamicSharedMemorySize, GEMM_SMEM);

    // ---- conversions + CSR build ----
    {
        int n4 = N_NODES * 512 / 4;
        conv_f2h_kernel<<<(n4 + 255) / 256, 256>>>(x, x16, n4);
        convT_f2h_kernel<<<(512 * 512 + 255) / 256, 256>>>(W1, w1t, 512, 512);
        convT_f2h_kernel<<<(256 * 512 + 255) / 256, 256>>>(W2, w2t, 256, 512);
    }
    cudaMemsetAsync(degp, 0, N_NODES * sizeof(int));
    count_kernel<<<(E_EDGES + 255) / 256, 256>>>(dst);
    scan_local_kernel<<<N_NODES / 512, 512>>>();
    scan_partial_kernel<<<1, 32>>>(N_NODES / 512);
    scan_add_kernel<<<N_NODES / 512, 512>>>();
    fill_kernel<<<(E_EDGES + 255) / 256, 256>>>(src, dst);

    // ---- layer 1 ----
    zero_parts_kernel<<<(N_NODES * 4 + 255) / 256, 256>>>(alsp, aldp, N_NODES * 4);
    {
        dim3 grid(4, N_NODES / 128);
        gemm_fp16_kernel<<<grid, 256, GEMM_SMEM>>>(x16, w1t, h16, a_s1, a_d1, alsp, aldp, 512);
    }
    gat_aggregate_warp<<<N_NODES / 8, 256>>>(h16, alsp, aldp, b1, nullptr, mh, 1);

    // ---- layer 2 ----
    zero_parts_kernel<<<(N_NODES * 4 + 255) / 256, 256>>>(alsp, aldp, N_NODES * 4);
    {
        dim3 grid(4, N_NODES / 128);
        gemm_fp16_kernel<<<grid, 256, GEMM_SMEM>>>(mh, w2t, h16, a_s2, a_d2, alsp, aldp, 256);
    }
    gat_aggregate_warp<<<N_NODES / 8, 256>>>(h16, alsp, aldp, b2, node_emb, nullptr, 0);

    // ---- temporal attention ----
    temporal_attn_kernel<<<NUM_AUD, 256>>>(node_emb, w_att, b_att, w_cls, b_cls, out_audio);
}

// round 8
// speedup vs baseline: 1.1550x; 1.1550x over previous
#include <cuda_runtime.h>
#include <cuda_fp16.h>
#include <math.h>
#include <stdint.h>

#define N_NODES   51200
#define NUM_AUD   64
#define NODES_PER 800
#define E_EDGES   409600
#define NEG       0.2f
#define BCAP      64

// ---------------- scratch ----------------------------------------------------
__device__ __half g_h16[(size_t)N_NODES * 512];
__device__ __half g_mh[(size_t)N_NODES * 256];
__device__ __half g_x16[(size_t)N_NODES * 512];
__device__ __half g_w1t[512 * 512];
__device__ __half g_w2t[512 * 256];
__device__ float  g_als[N_NODES * 2];
__device__ float  g_ald[N_NODES * 2];
__device__ int    g_deg[N_NODES];
__device__ int    g_bucket[(size_t)N_NODES * BCAP];

// ---------------- PTX helpers --------------------------------------------------
__device__ __forceinline__ uint32_t smem_u32(const void* p) {
    uint32_t a;
    asm("{ .reg .u64 t; cvta.to.shared.u64 t, %1; cvt.u32.u64 %0, t; }" : "=r"(a) : "l"(p));
    return a;
}
#define CP_ASYNC16(sa, ga) asm volatile("cp.async.cg.shared.global [%0], [%1], 16;" :: "r"(sa), "l"(ga))
#define CP_COMMIT()        asm volatile("cp.async.commit_group;" ::: "memory")
#define CP_WAIT(n)         asm volatile("cp.async.wait_group %0;" :: "n"(n) : "memory")

#define LDMATRIX_X4(r0, r1, r2, r3, ad) \
    asm volatile("ldmatrix.sync.aligned.m8n8.x4.shared.b16 {%0,%1,%2,%3}, [%4];" \
        : "=r"(r0), "=r"(r1), "=r"(r2), "=r"(r3) : "r"(ad))

#define MMA_FP16(c, a0, a1, a2, a3, b0, b1) \
    asm volatile("mma.sync.aligned.m16n8k16.row.col.f32.f16.f16.f32 " \
        "{%0,%1,%2,%3}, {%4,%5,%6,%7}, {%8,%9}, {%0,%1,%2,%3};" \
        : "+f"((c)[0]), "+f"((c)[1]), "+f"((c)[2]), "+f"((c)[3]) \
        : "r"(a0), "r"(a1), "r"(a2), "r"(a3), "r"(b0), "r"(b1))

// ---------------- fp16 GEMM (R5 config: 3-stage, 1 CTA/SM) ---------------------
#define ROWB   80
#define A_TILE (128 * ROWB)
#define B_TILE (128 * ROWB)
#define STAGE  (A_TILE + B_TILE)
#define NSTAGE 3
#define GEMM_SMEM (NSTAGE * STAGE + 1024)

__global__ void __launch_bounds__(256)
gemm_fp16_kernel(const __half* __restrict__ A, const __half* __restrict__ Bt,
                 __half* __restrict__ C,
                 const float* __restrict__ a_s, const float* __restrict__ a_d,
                 float* __restrict__ als, float* __restrict__ ald, int K) {
    extern __shared__ char smem[];
    const uint32_t sb = smem_u32(smem);
    float* s_as = (float*)(smem + NSTAGE * STAGE);
    float* s_ad = s_as + 128;

    const int tid = threadIdx.x;
    const int lane = tid & 31;
    const int wid = tid >> 5;
    const int warp_m = wid >> 1;
    const int warp_n = wid & 1;
    const int n0 = blockIdx.x * 128;
    const int m0 = blockIdx.y * 128;
    const int head = n0 >> 8;
    const int nin = n0 & 255;

    if (tid < 128) s_as[tid] = a_s[head * 256 + nin + tid];
    else           s_ad[tid - 128] = a_d[head * 256 + nin + tid - 128];

    const int ld_r = tid >> 2;
    const int ld_c = (tid & 3) << 4;

    const int a_row_l = warp_m * 32 + (lane & 15);
    const int a_colb  = (lane >> 4) << 4;
    const int bg = lane >> 3;
    const int b_row_base = warp_n * 64 + ((bg >> 1) << 3) + (lane & 7);
    const int b_colb  = (bg & 1) << 4;

    float acc[2][8][4];
#pragma unroll
    for (int i = 0; i < 2; ++i)
#pragma unroll
        for (int j = 0; j < 8; ++j)
#pragma unroll
            for (int k = 0; k < 4; ++k) acc[i][j][k] = 0.f;

    const int nch = K >> 5;

#define PREFETCH(CH) do { \
    const int k0 = (CH) << 5; \
    const uint32_t st = sb + ((CH) % NSTAGE) * STAGE; \
    _Pragma("unroll") \
    for (int hh = 0; hh < 2; ++hh) { \
        int r = ld_r + hh * 64; \
        CP_ASYNC16(st + r * ROWB + ld_c, A + (size_t)(m0 + r) * K + k0 + (ld_c >> 1)); \
    } \
    _Pragma("unroll") \
    for (int hh = 0; hh < 2; ++hh) { \
        int r = ld_r + hh * 64; \
        CP_ASYNC16(st + A_TILE + r * ROWB + ld_c, Bt + (size_t)(n0 + r) * K + k0 + (ld_c >> 1)); \
    } \
} while (0)

    PREFETCH(0); CP_COMMIT();
    PREFETCH(1); CP_COMMIT();

    for (int ch = 0; ch < nch; ++ch) {
        if (ch + 2 < nch) { PREFETCH(ch + 2); CP_COMMIT(); CP_WAIT(2); }
        else if (ch + 1 < nch) { CP_WAIT(1); }
        else { CP_WAIT(0); }
        __syncthreads();

        const uint32_t st = sb + (ch % NSTAGE) * STAGE;
#pragma unroll
        for (int ks = 0; ks < 2; ++ks) {
            const int kb = ks * 32;
            uint32_t a[2][4], b[4][4];
#pragma unroll
            for (int mt = 0; mt < 2; ++mt) {
                uint32_t ad = st + (a_row_l + mt * 16) * ROWB + kb + a_colb;
                LDMATRIX_X4(a[mt][0], a[mt][1], a[mt][2], a[mt][3], ad);
            }
#pragma unroll
            for (int np = 0; np < 4; ++np) {
                uint32_t ad = st + A_TILE + (b_row_base + np * 16) * ROWB + kb + b_colb;
                LDMATRIX_X4(b[np][0], b[np][1], b[np][2], b[np][3], ad);
            }
#pragma unroll
            for (int mt = 0; mt < 2; ++mt)
#pragma unroll
                for (int np = 0; np < 4; ++np)
#pragma unroll
                    for (int half = 0; half < 2; ++half)
                        MMA_FP16(acc[mt][np * 2 + half],
                                 a[mt][0], a[mt][1], a[mt][2], a[mt][3],
                                 b[np][half * 2], b[np][half * 2 + 1]);
        }
        __syncthreads();
    }

    const int g = lane >> 2;
    const int cpair = (lane & 3) << 1;
#pragma unroll
    for (int mt = 0; mt < 2; ++mt) {
        const int r0g = m0 + warp_m * 32 + mt * 16 + g;
        float ps0 = 0.f, pd0 = 0.f, ps1 = 0.f, pd1 = 0.f;
#pragma unroll
        for (int nt = 0; nt < 8; ++nt) {
            const int colL = warp_n * 64 + nt * 8 + cpair;
            float* c = acc[mt][nt];
            *(__half2*)(C + (size_t)r0g * 512 + n0 + colL) = __floats2half2_rn(c[0], c[1]);
            *(__half2*)(C + (size_t)(r0g + 8) * 512 + n0 + colL) = __floats2half2_rn(c[2], c[3]);
            ps0 += c[0] * s_as[colL] + c[1] * s_as[colL + 1];
            pd0 += c[0] * s_ad[colL] + c[1] * s_ad[colL + 1];
            ps1 += c[2] * s_as[colL] + c[3] * s_as[colL + 1];
            pd1 += c[2] * s_ad[colL] + c[3] * s_ad[colL + 1];
        }
#pragma unroll
        for (int o = 1; o <= 2; o <<= 1) {
            ps0 += __shfl_xor_sync(0xffffffffu, ps0, o);
            pd0 += __shfl_xor_sync(0xffffffffu, pd0, o);
            ps1 += __shfl_xor_sync(0xffffffffu, ps1, o);
            pd1 += __shfl_xor_sync(0xffffffffu, pd1, o);
        }
        if ((lane & 3) == 0) {
            atomicAdd(als + r0g * 2 + head, ps0);
            atomicAdd(ald + r0g * 2 + head, pd0);
            atomicAdd(als + (r0g + 8) * 2 + head, ps1);
            atomicAdd(ald + (r0g + 8) * 2 + head, pd1);
        }
    }
}

// ---------------- conversions ----------------------------------------------------
__global__ void conv_f2h_kernel(const float* __restrict__ in, __half* __restrict__ out, int n4) {
    int i = blockIdx.x * blockDim.x + threadIdx.x;
    if (i >= n4) return;
    float4 v = ((const float4*)in)[i];
    ((__half2*)out)[2 * i + 0] = __floats2half2_rn(v.x, v.y);
    ((__half2*)out)[2 * i + 1] = __floats2half2_rn(v.z, v.w);
}
__global__ void convT_f2h_kernel(const float* __restrict__ W, __half* __restrict__ Wt, int K, int Nn) {
    int o = blockIdx.x * blockDim.x + threadIdx.x;
    if (o >= K * Nn) return;
    int n = o / K, k = o - n * K;
    Wt[o] = __float2half(W[(size_t)k * Nn + n]);
}

// ---------------- direct-bucket CSR -------------------------------------------
__global__ void bucket_fill_kernel(const int* __restrict__ src, const int* __restrict__ dst) {
    int e = blockIdx.x * blockDim.x + threadIdx.x;
    if (e < E_EDGES) {
        int d = dst[e];
        int pos = atomicAdd(&g_deg[d], 1);
        if (pos < BCAP - 1) g_bucket[(size_t)d * BCAP + pos] = src[e];
    }
}

// ---------------- GAT aggregation: one warp per dst node, uint4 gather ----------
__global__ void __launch_bounds__(256)
gat_aggregate_warp(const __half* __restrict__ h,
                   const float* __restrict__ als, const float* __restrict__ ald,
                   const float* __restrict__ bias,
                   float* __restrict__ out32, __half* __restrict__ out16,
                   int do_relu) {
    __shared__ int   s_src[8][BCAP];
    __shared__ float s_a0[8][BCAP], s_a1[8][BCAP];
    const int w = threadIdx.x >> 5, lane = threadIdx.x & 31;
    const int d = blockIdx.x * 8 + w;
    const int deg = min(g_deg[d], BCAP - 1);
    const int tot = deg + 1;
    const float ad0 = ald[2 * d], ad1 = ald[2 * d + 1];
    const int* bkt = g_bucket + (size_t)d * BCAP;

    float m0 = -INFINITY, m1 = -INFINITY;
    for (int k = lane; k < tot; k += 32) {
        int s = (k < deg) ? bkt[k] : d;
        float e0 = als[2 * s] + ad0;     e0 = e0 > 0.f ? e0 : NEG * e0;
        float e1 = als[2 * s + 1] + ad1; e1 = e1 > 0.f ? e1 : NEG * e1;
        s_src[w][k] = s;
        s_a0[w][k] = e0;
        s_a1[w][k] = e1;
        m0 = fmaxf(m0, e0);
        m1 = fmaxf(m1, e1);
    }
#pragma unroll
    for (int o = 16; o; o >>= 1) {
        m0 = fmaxf(m0, __shfl_xor_sync(0xffffffffu, m0, o));
        m1 = fmaxf(m1, __shfl_xor_sync(0xffffffffu, m1, o));
    }
    __syncwarp();
    float q0 = 0.f, q1 = 0.f;
    for (int k = lane; k < tot; k += 32) {
        float w0 = __expf(s_a0[w][k] - m0);
        float w1 = __expf(s_a1[w][k] - m1);
        s_a0[w][k] = w0;
        s_a1[w][k] = w1;
        q0 += w0;
        q1 += w1;
    }
#pragma unroll
    for (int o = 16; o; o >>= 1) {
        q0 += __shfl_xor_sync(0xffffffffu, q0, o);
        q1 += __shfl_xor_sync(0xffffffffu, q1, o);
    }
    const float inv0 = 1.f / q0, inv1 = 1.f / q1;
    __syncwarp();

    // lane covers channels [8*lane, 8*lane+8) per head; one uint4 per head per row
    float acc0[8] = {}, acc1[8] = {};
    for (int k = 0; k < tot; ++k) {
        const int s = s_src[w][k];
        const float al0 = s_a0[w][k] * inv0;
        const float al1 = s_a1[w][k] * inv1;
        const __half* row = h + (size_t)s * 512;
        uint4 u0 = *(const uint4*)(row + 8 * lane);
        uint4 u1 = *(const uint4*)(row + 256 + 8 * lane);
        const __half2* p0 = (const __half2*)&u0;
        const __half2* p1 = (const __half2*)&u1;
#pragma unroll
        for (int j = 0; j < 4; ++j) {
            float2 v0 = __half22float2(p0[j]);
            float2 v1 = __half22float2(p1[j]);
            acc0[2 * j + 0] += al0 * v0.x;
            acc0[2 * j + 1] += al0 * v0.y;
            acc1[2 * j + 0] += al1 * v1.x;
            acc1[2 * j + 1] += al1 * v1.y;
        }
    }
    const int c0 = 8 * lane;
    float4 ob0, ob1;
    float vv[8];
#pragma unroll
    for (int j = 0; j < 8; ++j) {
        float v = 0.5f * (acc0[j] + acc1[j]) + bias[c0 + j];
        if (do_relu) v = fmaxf(v, 0.f);
        vv[j] = v;
    }
    if (out32) {
        ob0 = make_float4(vv[0], vv[1], vv[2], vv[3]);
        ob1 = make_float4(vv[4], vv[5], vv[6], vv[7]);
        *(float4*)(out32 + (size_t)d * 256 + c0) = ob0;
        *(float4*)(out32 + (size_t)d * 256 + c0 + 4) = ob1;
    }
    if (out16) {
        __half2 hh[4];
#pragma unroll
        for (int j = 0; j < 4; ++j) hh[j] = __floats2half2_rn(vv[2 * j], vv[2 * j + 1]);
        *(uint4*)(out16 + (size_t)d * 256 + c0) = *(uint4*)hh;
    }
}

// ---------------- temporal attention ------------------------------------------
__global__ void temporal_attn_kernel(const float* __restrict__ emb,
                                     const float* __restrict__ w_att,
                                     const float* __restrict__ b_att,
                                     const float* __restrict__ w_cls,
                                     const float* __restrict__ b_cls,
                                     float* __restrict__ out_audio) {
    const int a = blockIdx.x;
    const int tid = threadIdx.x;
    __shared__ float swa[256];
    __shared__ float slog[NODES_PER];
    __shared__ float sred[256];
    swa[tid] = w_att[tid];
    __syncthreads();
    const int base = a * NODES_PER;
    const int warp = tid >> 5, lane = tid & 31;
    for (int i = warp; i < NODES_PER; i += 8) {
        const float* row = emb + (size_t)(base + i) * 256;
        float p = 0.f;
#pragma unroll
        for (int c = lane; c < 256; c += 32) p += row[c] * swa[c];
#pragma unroll
        for (int o = 16; o; o >>= 1) p += __shfl_xor_sync(0xffffffffu, p, o);
        if (lane == 0) slog[i] = p + b_att[0];
    }
    __syncthreads();
    float m = -INFINITY;
    for (int i = tid; i < NODES_PER; i += 256) m = fmaxf(m, slog[i]);
    sred[tid] = m; __syncthreads();
    for (int o = 128; o; o >>= 1) { if (tid < o) sred[tid] = fmaxf(sred[tid], sred[tid + o]); __syncthreads(); }
    m = sred[0]; __syncthreads();
    float q = 0.f;
    for (int i = tid; i < NODES_PER; i += 256) { float w = expf(slog[i] - m); slog[i] = w; q += w; }
    sred[tid] = q; __syncthreads();
    for (int o = 128; o; o >>= 1) { if (tid < o) sred[tid] += sred[tid + o]; __syncthreads(); }
    float inv = 1.f / sred[0];
    __syncthreads();

    float ac0 = 0.f, ac1 = 0.f, ac2 = 0.f, ac3 = 0.f;
    for (int i = 0; i + 4 <= NODES_PER; i += 4) {
        ac0 += slog[i + 0] * emb[(size_t)(base + i + 0) * 256 + tid];
        ac1 += slog[i + 1] * emb[(size_t)(base + i + 1) * 256 + tid];
        ac2 += slog[i + 2] * emb[(size_t)(base + i + 2) * 256 + tid];
        ac3 += slog[i + 3] * emb[(size_t)(base + i + 3) * 256 + tid];
    }
    float acc = ((ac0 + ac1) + (ac2 + ac3)) * inv;

    float r0 = acc * w_cls[tid * 2 + 0];
    float r1 = acc * w_cls[tid * 2 + 1];
    sred[tid] = r0; __syncthreads();
    for (int o = 128; o; o >>= 1) { if (tid < o) sred[tid] += sred[tid + o]; __syncthreads(); }
    r0 = sred[0]; __syncthreads();
    sred[tid] = r1; __syncthreads();
    for (int o = 128; o; o >>= 1) { if (tid < o) sred[tid] += sred[tid + o]; __syncthreads(); }
    r1 = sred[0];
    if (tid == 0) {
        out_audio[a * 2 + 0] = r0 + b_cls[0];
        out_audio[a * 2 + 1] = r1 + b_cls[1];
    }
}

// ---------------- launch -------------------------------------------------------
extern "C" void kernel_launch(void* const* d_in, const int* in_sizes, int n_in,
                              void* d_out, int out_size) {
    const float* x     = (const float*)d_in[0];
    const int*   eidx  = (const int*)d_in[1];
    const float* W1    = (const float*)d_in[3];
    const float* a_s1  = (const float*)d_in[4];
    const float* a_d1  = (const float*)d_in[5];
    const float* b1    = (const float*)d_in[6];
    const float* W2    = (const float*)d_in[7];
    const float* a_s2  = (const float*)d_in[8];
    const float* a_d2  = (const float*)d_in[9];
    const float* b2    = (const float*)d_in[10];
    const float* w_att = (const float*)d_in[11];
    const float* b_att = (const float*)d_in[12];
    const float* w_cls = (const float*)d_in[13];
    const float* b_cls = (const float*)d_in[14];

    const int* src = eidx;
    const int* dst = eidx + E_EDGES;

    float* node_emb  = (float*)d_out;
    float* out_audio = (float*)d_out + (size_t)N_NODES * 256;

    void* p;
    cudaGetSymbolAddress(&p, g_h16);  __half* h16  = (__half*)p;
    cudaGetSymbolAddress(&p, g_mh);   __half* mh   = (__half*)p;
    cudaGetSymbolAddress(&p, g_x16);  __half* x16  = (__half*)p;
    cudaGetSymbolAddress(&p, g_w1t);  __half* w1t  = (__half*)p;
    cudaGetSymbolAddress(&p, g_w2t);  __half* w2t  = (__half*)p;
    cudaGetSymbolAddress(&p, g_als);  float*  als  = (float*)p;
    cudaGetSymbolAddress(&p, g_ald);  float*  ald  = (float*)p;
    cudaGetSymbolAddress(&p, g_deg);  int*    degp = (int*)p;

    cudaFuncSetAttribute(gemm_fp16_kernel, cudaFuncAttributeMaxDynamicSharedMemorySize, GEMM_SMEM);

    // ---- conversions + direct-bucket CSR ----
    {
        int n4 = N_NODES * 512 / 4;
        conv_f2h_kernel<<<(n4 + 255) / 256, 256>>>(x, x16, n4);
        convT_f2h_kernel<<<(512 * 512 + 255) / 256, 256>>>(W1, w1t, 512, 512);
        convT_f2h_kernel<<<(256 * 512 + 255) / 256, 256>>>(W2, w2t, 256, 512);
    }
    cudaMemsetAsync(degp, 0, N_NODES * sizeof(int));
    bucket_fill_kernel<<<(E_EDGES + 255) / 256, 256>>>(src, dst);

    // ---- layer 1 ----
    cudaMemsetAsync(als, 0, N_NODES * 2 * sizeof(float));
    cudaMemsetAsync(ald, 0, N_NODES * 2 * sizeof(float));
    {
        dim3 grid(4, N_NODES / 128);
        gemm_fp16_kernel<<<grid, 256, GEMM_SMEM>>>(x16, w1t, h16, a_s1, a_d1, als, ald, 512);
    }
    gat_aggregate_warp<<<N_NODES / 8, 256>>>(h16, als, ald, b1, nullptr, mh, 1);

    // ---- layer 2 ----
    cudaMemsetAsync(als, 0, N_NODES * 2 * sizeof(float));
    cudaMemsetAsync(ald, 0, N_NODES * 2 * sizeof(float));
    {
        dim3 grid(4, N_NODES / 128);
        gemm_fp16_kernel<<<grid, 256, GEMM_SMEM>>>(mh, w2t, h16, a_s2, a_d2, als, ald, 256);
    }
    gat_aggregate_warp<<<N_NODES / 8, 256>>>(h16, als, ald, b2, node_emb, nullptr, 0);

    // ---- temporal attention ----
    temporal_attn_kernel<<<NUM_AUD, 256>>>(node_emb, w_att, b_att, w_cls, b_cls, out_audio);
}

// round 9
// speedup vs baseline: 1.2901x; 1.1170x over previous
#include <cuda_runtime.h>
#include <cuda_fp16.h>
#include <math.h>
#include <stdint.h>

#define N_NODES   51200
#define NUM_AUD   64
#define NODES_PER 800
#define E_EDGES   409600
#define NEG       0.2f
#define BCAP      64

// ---------------- scratch ----------------------------------------------------
__device__ __half g_h16[(size_t)N_NODES * 512];
__device__ __half g_mh[(size_t)N_NODES * 256];
__device__ __half g_emb16[(size_t)N_NODES * 256];
__device__ __half g_x16[(size_t)N_NODES * 512];
__device__ __half g_w1t[512 * 512];
__device__ __half g_w2t[512 * 256];
__device__ float  g_als[N_NODES * 2];
__device__ float  g_ald[N_NODES * 2];
__device__ int    g_deg[N_NODES];
__device__ int    g_bucket[(size_t)N_NODES * BCAP];

// ---------------- PTX helpers --------------------------------------------------
__device__ __forceinline__ uint32_t smem_u32(const void* p) {
    uint32_t a;
    asm("{ .reg .u64 t; cvta.to.shared.u64 t, %1; cvt.u32.u64 %0, t; }" : "=r"(a) : "l"(p));
    return a;
}
#define CP_ASYNC16(sa, ga) asm volatile("cp.async.cg.shared.global [%0], [%1], 16;" :: "r"(sa), "l"(ga))
#define CP_COMMIT()        asm volatile("cp.async.commit_group;" ::: "memory")
#define CP_WAIT(n)         asm volatile("cp.async.wait_group %0;" :: "n"(n) : "memory")

#define LDMATRIX_X4(r0, r1, r2, r3, ad) \
    asm volatile("ldmatrix.sync.aligned.m8n8.x4.shared.b16 {%0,%1,%2,%3}, [%4];" \
        : "=r"(r0), "=r"(r1), "=r"(r2), "=r"(r3) : "r"(ad))

#define MMA_FP16(c, a0, a1, a2, a3, b0, b1) \
    asm volatile("mma.sync.aligned.m16n8k16.row.col.f32.f16.f16.f32 " \
        "{%0,%1,%2,%3}, {%4,%5,%6,%7}, {%8,%9}, {%0,%1,%2,%3};" \
        : "+f"((c)[0]), "+f"((c)[1]), "+f"((c)[2]), "+f"((c)[3]) \
        : "r"(a0), "r"(a1), "r"(a2), "r"(a3), "r"(b0), "r"(b1))

// ---------------- fp16 GEMM: 4-stage, 1 sync/chunk, 1 CTA/SM -------------------
#define ROWB   80
#define A_TILE (128 * ROWB)
#define B_TILE (128 * ROWB)
#define STAGE  (A_TILE + B_TILE)
#define NSTAGE 4
#define GEMM_SMEM (NSTAGE * STAGE + 1024)

__global__ void __launch_bounds__(256)
gemm_fp16_kernel(const __half* __restrict__ A, const __half* __restrict__ Bt,
                 __half* __restrict__ C,
                 const float* __restrict__ a_s, const float* __restrict__ a_d,
                 float* __restrict__ als, float* __restrict__ ald, int K) {
    extern __shared__ char smem[];
    const uint32_t sb = smem_u32(smem);
    float* s_as = (float*)(smem + NSTAGE * STAGE);
    float* s_ad = s_as + 128;

    const int tid = threadIdx.x;
    const int lane = tid & 31;
    const int wid = tid >> 5;
    const int warp_m = wid >> 1;
    const int warp_n = wid & 1;
    const int n0 = blockIdx.x * 128;
    const int m0 = blockIdx.y * 128;
    const int head = n0 >> 8;
    const int nin = n0 & 255;

    if (tid < 128) s_as[tid] = a_s[head * 256 + nin + tid];
    else           s_ad[tid - 128] = a_d[head * 256 + nin + tid - 128];

    const int ld_r = tid >> 2;
    const int ld_c = (tid & 3) << 4;

    const int a_row_l = warp_m * 32 + (lane & 15);
    const int a_colb  = (lane >> 4) << 4;
    const int bg = lane >> 3;
    const int b_row_base = warp_n * 64 + ((bg >> 1) << 3) + (lane & 7);
    const int b_colb  = (bg & 1) << 4;

    float acc[2][8][4];
#pragma unroll
    for (int i = 0; i < 2; ++i)
#pragma unroll
        for (int j = 0; j < 8; ++j)
#pragma unroll
            for (int k = 0; k < 4; ++k) acc[i][j][k] = 0.f;

    const int nch = K >> 5;

#define PREFETCH(CH) do { \
    const int k0 = (CH) << 5; \
    const uint32_t st = sb + ((CH) & (NSTAGE - 1)) * STAGE; \
    _Pragma("unroll") \
    for (int hh = 0; hh < 2; ++hh) { \
        int r = ld_r + hh * 64; \
        CP_ASYNC16(st + r * ROWB + ld_c, A + (size_t)(m0 + r) * K + k0 + (ld_c >> 1)); \
    } \
    _Pragma("unroll") \
    for (int hh = 0; hh < 2; ++hh) { \
        int r = ld_r + hh * 64; \
        CP_ASYNC16(st + A_TILE + r * ROWB + ld_c, Bt + (size_t)(n0 + r) * K + k0 + (ld_c >> 1)); \
    } \
} while (0)

    PREFETCH(0); CP_COMMIT();
    PREFETCH(1); CP_COMMIT();
    PREFETCH(2); CP_COMMIT();

    for (int ch = 0; ch < nch; ++ch) {
        CP_WAIT(2);          // group ch complete
        __syncthreads();     // single barrier per chunk

        const uint32_t st = sb + (ch & (NSTAGE - 1)) * STAGE;
#pragma unroll
        for (int ks = 0; ks < 2; ++ks) {
            const int kb = ks * 32;
            uint32_t a[2][4], b[4][4];
#pragma unroll
            for (int mt = 0; mt < 2; ++mt) {
                uint32_t ad = st + (a_row_l + mt * 16) * ROWB + kb + a_colb;
                LDMATRIX_X4(a[mt][0], a[mt][1], a[mt][2], a[mt][3], ad);
            }
#pragma unroll
            for (int np = 0; np < 4; ++np) {
                uint32_t ad = st + A_TILE + (b_row_base + np * 16) * ROWB + kb + b_colb;
                LDMATRIX_X4(b[np][0], b[np][1], b[np][2], b[np][3], ad);
            }
#pragma unroll
            for (int mt = 0; mt < 2; ++mt)
#pragma unroll
                for (int np = 0; np < 4; ++np)
#pragma unroll
                    for (int half = 0; half < 2; ++half)
                        MMA_FP16(acc[mt][np * 2 + half],
                                 a[mt][0], a[mt][1], a[mt][2], a[mt][3],
                                 b[np][half * 2], b[np][half * 2 + 1]);
        }
        if (ch + 3 < nch) { PREFETCH(ch + 3); CP_COMMIT(); }
    }

    const int g = lane >> 2;
    const int cpair = (lane & 3) << 1;
#pragma unroll
    for (int mt = 0; mt < 2; ++mt) {
        const int r0g = m0 + warp_m * 32 + mt * 16 + g;
        float ps0 = 0.f, pd0 = 0.f, ps1 = 0.f, pd1 = 0.f;
#pragma unroll
        for (int nt = 0; nt < 8; ++nt) {
            const int colL = warp_n * 64 + nt * 8 + cpair;
            float* c = acc[mt][nt];
            *(__half2*)(C + (size_t)r0g * 512 + n0 + colL) = __floats2half2_rn(c[0], c[1]);
            *(__half2*)(C + (size_t)(r0g + 8) * 512 + n0 + colL) = __floats2half2_rn(c[2], c[3]);
            ps0 += c[0] * s_as[colL] + c[1] * s_as[colL + 1];
            pd0 += c[0] * s_ad[colL] + c[1] * s_ad[colL + 1];
            ps1 += c[2] * s_as[colL] + c[3] * s_as[colL + 1];
            pd1 += c[2] * s_ad[colL] + c[3] * s_ad[colL + 1];
        }
#pragma unroll
        for (int o = 1; o <= 2; o <<= 1) {
            ps0 += __shfl_xor_sync(0xffffffffu, ps0, o);
            pd0 += __shfl_xor_sync(0xffffffffu, pd0, o);
            ps1 += __shfl_xor_sync(0xffffffffu, ps1, o);
            pd1 += __shfl_xor_sync(0xffffffffu, pd1, o);
        }
        if ((lane & 3) == 0) {
            atomicAdd(als + r0g * 2 + head, ps0);
            atomicAdd(ald + r0g * 2 + head, pd0);
            atomicAdd(als + (r0g + 8) * 2 + head, ps1);
            atomicAdd(ald + (r0g + 8) * 2 + head, pd1);
        }
    }
}

// ---------------- conversions ----------------------------------------------------
__global__ void conv_f2h_kernel(const float* __restrict__ in, __half* __restrict__ out, int n4) {
    int i = blockIdx.x * blockDim.x + threadIdx.x;
    if (i >= n4) return;
    float4 v = ((const float4*)in)[i];
    ((__half2*)out)[2 * i + 0] = __floats2half2_rn(v.x, v.y);
    ((__half2*)out)[2 * i + 1] = __floats2half2_rn(v.z, v.w);
}
__global__ void convT_f2h_kernel(const float* __restrict__ W, __half* __restrict__ Wt, int K, int Nn) {
    int o = blockIdx.x * blockDim.x + threadIdx.x;
    if (o >= K * Nn) return;
    int n = o / K, k = o - n * K;
    Wt[o] = __float2half(W[(size_t)k * Nn + n]);
}

// ---------------- direct-bucket CSR -------------------------------------------
__global__ void bucket_fill_kernel(const int* __restrict__ src, const int* __restrict__ dst) {
    int e = blockIdx.x * blockDim.x + threadIdx.x;
    if (e < E_EDGES) {
        int d = dst[e];
        int pos = atomicAdd(&g_deg[d], 1);
        if (pos < BCAP - 1) g_bucket[(size_t)d * BCAP + pos] = src[e];
    }
}

// ---------------- GAT aggregation: one warp per dst node, uint4 gather ----------
__global__ void __launch_bounds__(256)
gat_aggregate_warp(const __half* __restrict__ h,
                   const float* __restrict__ als, const float* __restrict__ ald,
                   const float* __restrict__ bias,
                   float* __restrict__ out32, __half* __restrict__ out16,
                   int do_relu) {
    __shared__ int   s_src[8][BCAP];
    __shared__ float s_a0[8][BCAP], s_a1[8][BCAP];
    const int w = threadIdx.x >> 5, lane = threadIdx.x & 31;
    const int d = blockIdx.x * 8 + w;
    const int deg = min(g_deg[d], BCAP - 1);
    const int tot = deg + 1;
    const float ad0 = ald[2 * d], ad1 = ald[2 * d + 1];
    const int* bkt = g_bucket + (size_t)d * BCAP;

    float m0 = -INFINITY, m1 = -INFINITY;
    for (int k = lane; k < tot; k += 32) {
        int s = (k < deg) ? bkt[k] : d;
        float e0 = als[2 * s] + ad0;     e0 = e0 > 0.f ? e0 : NEG * e0;
        float e1 = als[2 * s + 1] + ad1; e1 = e1 > 0.f ? e1 : NEG * e1;
        s_src[w][k] = s;
        s_a0[w][k] = e0;
        s_a1[w][k] = e1;
        m0 = fmaxf(m0, e0);
        m1 = fmaxf(m1, e1);
    }
#pragma unroll
    for (int o = 16; o; o >>= 1) {
        m0 = fmaxf(m0, __shfl_xor_sync(0xffffffffu, m0, o));
        m1 = fmaxf(m1, __shfl_xor_sync(0xffffffffu, m1, o));
    }
    __syncwarp();
    float q0 = 0.f, q1 = 0.f;
    for (int k = lane; k < tot; k += 32) {
        float w0 = __expf(s_a0[w][k] - m0);
        float w1 = __expf(s_a1[w][k] - m1);
        s_a0[w][k] = w0;
        s_a1[w][k] = w1;
        q0 += w0;
        q1 += w1;
    }
#pragma unroll
    for (int o = 16; o; o >>= 1) {
        q0 += __shfl_xor_sync(0xffffffffu, q0, o);
        q1 += __shfl_xor_sync(0xffffffffu, q1, o);
    }
    const float inv0 = 1.f / q0, inv1 = 1.f / q1;
    __syncwarp();

    float acc0[8] = {}, acc1[8] = {};
    for (int k = 0; k < tot; ++k) {
        const int s = s_src[w][k];
        const float al0 = s_a0[w][k] * inv0;
        const float al1 = s_a1[w][k] * inv1;
        const __half* row = h + (size_t)s * 512;
        uint4 u0 = *(const uint4*)(row + 8 * lane);
        uint4 u1 = *(const uint4*)(row + 256 + 8 * lane);
        const __half2* p0 = (const __half2*)&u0;
        const __half2* p1 = (const __half2*)&u1;
#pragma unroll
        for (int j = 0; j < 4; ++j) {
            float2 v0 = __half22float2(p0[j]);
            float2 v1 = __half22float2(p1[j]);
            acc0[2 * j + 0] += al0 * v0.x;
            acc0[2 * j + 1] += al0 * v0.y;
            acc1[2 * j + 0] += al1 * v1.x;
            acc1[2 * j + 1] += al1 * v1.y;
        }
    }
    const int c0 = 8 * lane;
    float vv[8];
#pragma unroll
    for (int j = 0; j < 8; ++j) {
        float v = 0.5f * (acc0[j] + acc1[j]) + bias[c0 + j];
        if (do_relu) v = fmaxf(v, 0.f);
        vv[j] = v;
    }
    if (out32) {
        *(float4*)(out32 + (size_t)d * 256 + c0) = make_float4(vv[0], vv[1], vv[2], vv[3]);
        *(float4*)(out32 + (size_t)d * 256 + c0 + 4) = make_float4(vv[4], vv[5], vv[6], vv[7]);
    }
    if (out16) {
        __half2 hh[4];
#pragma unroll
        for (int j = 0; j < 4; ++j) hh[j] = __floats2half2_rn(vv[2 * j], vv[2 * j + 1]);
        *(uint4*)(out16 + (size_t)d * 256 + c0) = *(uint4*)hh;
    }
}

// ---------------- temporal attention (fp16 emb reads) ---------------------------
__global__ void temporal_attn_kernel(const __half* __restrict__ emb16,
                                     const float* __restrict__ w_att,
                                     const float* __restrict__ b_att,
                                     const float* __restrict__ w_cls,
                                     const float* __restrict__ b_cls,
                                     float* __restrict__ out_audio) {
    const int a = blockIdx.x;
    const int tid = threadIdx.x;
    __shared__ float swa[256];
    __shared__ float slog[NODES_PER];
    __shared__ float sred[256];
    swa[tid] = w_att[tid];
    __syncthreads();
    const int base = a * NODES_PER;
    const int warp = tid >> 5, lane = tid & 31;
    for (int i = warp; i < NODES_PER; i += 8) {
        const __half2* row = (const __half2*)(emb16 + (size_t)(base + i) * 256);
        float p = 0.f;
#pragma unroll
        for (int c = lane; c < 128; c += 32) {
            float2 v = __half22float2(row[c]);
            p += v.x * swa[2 * c] + v.y * swa[2 * c + 1];
        }
#pragma unroll
        for (int o = 16; o; o >>= 1) p += __shfl_xor_sync(0xffffffffu, p, o);
        if (lane == 0) slog[i] = p + b_att[0];
    }
    __syncthreads();
    float m = -INFINITY;
    for (int i = tid; i < NODES_PER; i += 256) m = fmaxf(m, slog[i]);
    sred[tid] = m; __syncthreads();
    for (int o = 128; o; o >>= 1) { if (tid < o) sred[tid] = fmaxf(sred[tid], sred[tid + o]); __syncthreads(); }
    m = sred[0]; __syncthreads();
    float q = 0.f;
    for (int i = tid; i < NODES_PER; i += 256) { float w = expf(slog[i] - m); slog[i] = w; q += w; }
    sred[tid] = q; __syncthreads();
    for (int o = 128; o; o >>= 1) { if (tid < o) sred[tid] += sred[tid + o]; __syncthreads(); }
    float inv = 1.f / sred[0];
    __syncthreads();

    float ac0 = 0.f, ac1 = 0.f, ac2 = 0.f, ac3 = 0.f;
    for (int i = 0; i + 4 <= NODES_PER; i += 4) {
        ac0 += slog[i + 0] * __half2float(emb16[(size_t)(base + i + 0) * 256 + tid]);
        ac1 += slog[i + 1] * __half2float(emb16[(size_t)(base + i + 1) * 256 + tid]);
        ac2 += slog[i + 2] * __half2float(emb16[(size_t)(base + i + 2) * 256 + tid]);
        ac3 += slog[i + 3] * __half2float(emb16[(size_t)(base + i + 3) * 256 + tid]);
    }
    float acc = ((ac0 + ac1) + (ac2 + ac3)) * inv;

    float r0 = acc * w_cls[tid * 2 + 0];
    float r1 = acc * w_cls[tid * 2 + 1];
    sred[tid] = r0; __syncthreads();
    for (int o = 128; o; o >>= 1) { if (tid < o) sred[tid] += sred[tid + o]; __syncthreads(); }
    r0 = sred[0]; __syncthreads();
    sred[tid] = r1; __syncthreads();
    for (int o = 128; o; o >>= 1) { if (tid < o) sred[tid] += sred[tid + o]; __syncthreads(); }
    r1 = sred[0];
    if (tid == 0) {
        out_audio[a * 2 + 0] = r0 + b_cls[0];
        out_audio[a * 2 + 1] = r1 + b_cls[1];
    }
}

// ---------------- launch -------------------------------------------------------
extern "C" void kernel_launch(void* const* d_in, const int* in_sizes, int n_in,
                              void* d_out, int out_size) {
    const float* x     = (const float*)d_in[0];
    const int*   eidx  = (const int*)d_in[1];
    const float* W1    = (const float*)d_in[3];
    const float* a_s1  = (const float*)d_in[4];
    const float* a_d1  = (const float*)d_in[5];
    const float* b1    = (const float*)d_in[6];
    const float* W2    = (const float*)d_in[7];
    const float* a_s2  = (const float*)d_in[8];
    const float* a_d2  = (const float*)d_in[9];
    const float* b2    = (const float*)d_in[10];
    const float* w_att = (const float*)d_in[11];
    const float* b_att = (const float*)d_in[12];
    const float* w_cls = (const float*)d_in[13];
    const float* b_cls = (const float*)d_in[14];

    const int* src = eidx;
    const int* dst = eidx + E_EDGES;

    float* node_emb  = (float*)d_out;
    float* out_audio = (float*)d_out + (size_t)N_NODES * 256;

    void* p;
    cudaGetSymbolAddress(&p, g_h16);   __half* h16   = (__half*)p;
    cudaGetSymbolAddress(&p, g_mh);    __half* mh    = (__half*)p;
    cudaGetSymbolAddress(&p, g_emb16); __half* emb16 = (__half*)p;
    cudaGetSymbolAddress(&p, g_x16);   __half* x16   = (__half*)p;
    cudaGetSymbolAddress(&p, g_w1t);   __half* w1t   = (__half*)p;
    cudaGetSymbolAddress(&p, g_w2t);   __half* w2t   = (__half*)p;
    cudaGetSymbolAddress(&p, g_als);   float*  als   = (float*)p;
    cudaGetSymbolAddress(&p, g_ald);   float*  ald   = (float*)p;
    cudaGetSymbolAddress(&p, g_deg);   int*    degp  = (int*)p;

    cudaFuncSetAttribute(gemm_fp16_kernel, cudaFuncAttributeMaxDynamicSharedMemorySize, GEMM_SMEM);

    // ---- conversions + direct-bucket CSR ----
    {
        int n4 = N_NODES * 512 / 4;
        conv_f2h_kernel<<<(n4 + 255) / 256, 256>>>(x, x16, n4);
        convT_f2h_kernel<<<(512 * 512 + 255) / 256, 256>>>(W1, w1t, 512, 512);
        convT_f2h_kernel<<<(256 * 512 + 255) / 256, 256>>>(W2, w2t, 256, 512);
    }
    cudaMemsetAsync(degp, 0, N_NODES * sizeof(int));
    bucket_fill_kernel<<<(E_EDGES + 255) / 256, 256>>>(src, dst);

    // ---- layer 1 ----
    cudaMemsetAsync(als, 0, N_NODES * 2 * sizeof(float));
    cudaMemsetAsync(ald, 0, N_NODES * 2 * sizeof(float));
    {
        dim3 grid(4, N_NODES / 128);
        gemm_fp16_kernel<<<grid, 256, GEMM_SMEM>>>(x16, w1t, h16, a_s1, a_d1, als, ald, 512);
    }
    gat_aggregate_warp<<<N_NODES / 8, 256>>>(h16, als, ald, b1, nullptr, mh, 1);

    // ---- layer 2 ----
    cudaMemsetAsync(als, 0, N_NODES * 2 * sizeof(float));
    cudaMemsetAsync(ald, 0, N_NODES * 2 * sizeof(float));
    {
        dim3 grid(4, N_NODES / 128);
        gemm_fp16_kernel<<<grid, 256, GEMM_SMEM>>>(mh, w2t, h16, a_s2, a_d2, als, ald, 256);
    }
    gat_aggregate_warp<<<N_NODES / 8, 256>>>(h16, als, ald, b2, node_emb, emb16, 0);

    // ---- temporal attention ----
    temporal_attn_kernel<<<NUM_AUD, 256>>>(emb16, w_att, b_att, w_cls, b_cls, out_audio);
}